// round 1
// baseline (speedup 1.0000x reference)
#include <cuda_runtime.h>
#include <math.h>

// FlashAttentionScore: B=2, N=16, S=2048, D=128, fp32, causal.
// d_out layout: [out: 32*2048*128][max x8: 32*2048*8][sum x8: 32*2048*8]

#define S_LEN 2048
#define DH    128
#define BM    64
#define BN    64
#define NTHREADS 256

// smem layout (floats), transposed Q/K rows padded to 68, V rows to 132
#define QT_OFF 0
#define KT_OFF (128*68)
#define VS_OFF (2*128*68)
#define PS_OFF (2*128*68 + 64*132)
#define SMEM_FLOATS (2*128*68 + 64*132 + 64*68)

__global__ void __launch_bounds__(NTHREADS, 1)
fa_causal_kernel(const float* __restrict__ q,
                 const float* __restrict__ k,
                 const float* __restrict__ v,
                 float* __restrict__ out,
                 float* __restrict__ omax,
                 float* __restrict__ osum)
{
    extern __shared__ float sm[];
    float* Qt = sm + QT_OFF;   // [128][68]  (d-major, row = query idx)
    float* Kt = sm + KT_OFF;   // [128][68]  (d-major, row = key idx)
    float* Vs = sm + VS_OFF;   // [64][132]  (natural)
    float* Ps = sm + PS_OFF;   // [64][68]   (exp scores)

    const int tid = threadIdx.x;
    const int h   = blockIdx.y;   // head (b*N+n), 0..31
    const int qt  = blockIdx.x;   // query tile, 0..31

    const float* Qg = q + ((size_t)h * S_LEN + (size_t)qt * BM) * DH;
    const float* Kg = k + (size_t)h * S_LEN * DH;
    const float* Vg = v + (size_t)h * S_LEN * DH;

    // transpose-load mapping: warp covers 8 rows x 4 consecutive float4's
    const int lt   = tid & 31;
    const int lw   = tid >> 5;
    const int trow = (lt >> 2) + 8 * lw;  // 0..63
    const int tc4  = (lt & 3);            // float4 sub-index

    // ---- load Q tile transposed (once) ----
#pragma unroll
    for (int it = 0; it < 8; ++it) {
        int d4 = tc4 + 4 * it;                       // 0..31
        float4 val = ((const float4*)Qg)[trow * 32 + d4];
        int dd = d4 * 4;
        Qt[(dd + 0) * 68 + trow] = val.x;
        Qt[(dd + 1) * 68 + trow] = val.y;
        Qt[(dd + 2) * 68 + trow] = val.z;
        Qt[(dd + 3) * 68 + trow] = val.w;
    }

    const int tx = tid & 15;   // score col group / out col group
    const int ty = tid >> 4;   // row group (rows 4*ty .. 4*ty+3)

    float m_i[4], l_i[4];
    float acc[4][8];
#pragma unroll
    for (int i = 0; i < 4; ++i) {
        m_i[i] = -1e30f;
        l_i[i] = 0.f;
#pragma unroll
        for (int j = 0; j < 8; ++j) acc[i][j] = 0.f;
    }

    const float SCALE = 0.08838834764831845f;  // 1/sqrt(128)
    const float LOG2E = 1.4426950408889634f;

    for (int kt = 0; kt <= qt; ++kt) {
        __syncthreads();  // previous iteration done with Kt/Vs/Ps

        const float* Kgt = Kg + (size_t)kt * BN * DH;
        const float* Vgt = Vg + (size_t)kt * BN * DH;

        // K tile -> transposed smem
#pragma unroll
        for (int it = 0; it < 8; ++it) {
            int d4 = tc4 + 4 * it;
            float4 val = ((const float4*)Kgt)[trow * 32 + d4];
            int dd = d4 * 4;
            Kt[(dd + 0) * 68 + trow] = val.x;
            Kt[(dd + 1) * 68 + trow] = val.y;
            Kt[(dd + 2) * 68 + trow] = val.z;
            Kt[(dd + 3) * 68 + trow] = val.w;
        }
        // V tile -> natural smem
#pragma unroll
        for (int it = 0; it < 8; ++it) {
            int e   = it * NTHREADS + tid;
            int row = e >> 5;
            int d4  = e & 31;
            ((float4*)(Vs + row * 132))[d4] = ((const float4*)Vgt)[row * 32 + d4];
        }
        __syncthreads();

        // ---- S = scale * Q K^T  (64x64, 4x4 per thread) ----
        float s[4][4];
#pragma unroll
        for (int i = 0; i < 4; ++i)
#pragma unroll
            for (int j = 0; j < 4; ++j) s[i][j] = 0.f;

#pragma unroll 8
        for (int d = 0; d < DH; ++d) {
            float4 a = *(const float4*)(Qt + d * 68 + 4 * ty);
            float4 b = *(const float4*)(Kt + d * 68 + 4 * tx);
            float av[4] = {a.x, a.y, a.z, a.w};
            float bv[4] = {b.x, b.y, b.z, b.w};
#pragma unroll
            for (int i = 0; i < 4; ++i)
#pragma unroll
                for (int j = 0; j < 4; ++j)
                    s[i][j] += av[i] * bv[j];
        }

        // scale + causal mask (only diagonal tile needs masking)
        if (kt == qt) {
#pragma unroll
            for (int i = 0; i < 4; ++i)
#pragma unroll
                for (int j = 0; j < 4; ++j) {
                    int r = 4 * ty + i, c = 4 * tx + j;
                    s[i][j] = (c <= r) ? s[i][j] * SCALE : -1e30f;
                }
        } else {
#pragma unroll
            for (int i = 0; i < 4; ++i)
#pragma unroll
                for (int j = 0; j < 4; ++j) s[i][j] *= SCALE;
        }

        // ---- online softmax (row groups of 16 lanes share a row) ----
#pragma unroll
        for (int i = 0; i < 4; ++i) {
            float tm = s[i][0];
#pragma unroll
            for (int j = 1; j < 4; ++j) tm = fmaxf(tm, s[i][j]);
#pragma unroll
            for (int o = 8; o > 0; o >>= 1)
                tm = fmaxf(tm, __shfl_xor_sync(0xffffffffu, tm, o));

            float m_new = fmaxf(m_i[i], tm);
            float alpha = exp2f((m_i[i] - m_new) * LOG2E);

            float rs = 0.f;
#pragma unroll
            for (int j = 0; j < 4; ++j) {
                s[i][j] = exp2f((s[i][j] - m_new) * LOG2E);
                rs += s[i][j];
            }
#pragma unroll
            for (int o = 8; o > 0; o >>= 1)
                rs += __shfl_xor_sync(0xffffffffu, rs, o);

            l_i[i] = l_i[i] * alpha + rs;
            m_i[i] = m_new;
#pragma unroll
            for (int j = 0; j < 8; ++j) acc[i][j] *= alpha;

            // write exp scores
            *(float4*)(Ps + (4 * ty + i) * 68 + 4 * tx) =
                make_float4(s[i][0], s[i][1], s[i][2], s[i][3]);
        }
        __syncthreads();

        // ---- acc += P @ V  (64x64 @ 64x128, 4x8 per thread) ----
#pragma unroll 4
        for (int k4 = 0; k4 < 16; ++k4) {
            float4 pv[4];
#pragma unroll
            for (int i = 0; i < 4; ++i)
                pv[i] = *(const float4*)(Ps + (4 * ty + i) * 68 + 4 * k4);
            float4 vv[4][2];
#pragma unroll
            for (int kk = 0; kk < 4; ++kk) {
                const float* vrow = Vs + (4 * k4 + kk) * 132 + 8 * tx;
                vv[kk][0] = *(const float4*)(vrow);
                vv[kk][1] = *(const float4*)(vrow + 4);
            }
#pragma unroll
            for (int i = 0; i < 4; ++i) {
                float pr[4] = {pv[i].x, pv[i].y, pv[i].z, pv[i].w};
#pragma unroll
                for (int kk = 0; kk < 4; ++kk) {
                    acc[i][0] += pr[kk] * vv[kk][0].x;
                    acc[i][1] += pr[kk] * vv[kk][0].y;
                    acc[i][2] += pr[kk] * vv[kk][0].z;
                    acc[i][3] += pr[kk] * vv[kk][0].w;
                    acc[i][4] += pr[kk] * vv[kk][1].x;
                    acc[i][5] += pr[kk] * vv[kk][1].y;
                    acc[i][6] += pr[kk] * vv[kk][1].z;
                    acc[i][7] += pr[kk] * vv[kk][1].w;
                }
            }
        }
    }

    // ---- epilogue ----
#pragma unroll
    for (int i = 0; i < 4; ++i) {
        int row  = 4 * ty + i;
        int qpos = qt * BM + row;
        float inv = 1.0f / l_i[i];
        float* orow = out + ((size_t)h * S_LEN + qpos) * DH + 8 * tx;
        float4 o0 = make_float4(acc[i][0] * inv, acc[i][1] * inv,
                                acc[i][2] * inv, acc[i][3] * inv);
        float4 o1 = make_float4(acc[i][4] * inv, acc[i][5] * inv,
                                acc[i][6] * inv, acc[i][7] * inv);
        *(float4*)(orow)     = o0;
        *(float4*)(orow + 4) = o1;

        if (tx == 0) {
            size_t sidx = ((size_t)h * S_LEN + qpos) * 8;
            float4 mv = make_float4(m_i[i], m_i[i], m_i[i], m_i[i]);
            float4 lv = make_float4(l_i[i], l_i[i], l_i[i], l_i[i]);
            *(float4*)(omax + sidx)     = mv;
            *(float4*)(omax + sidx + 4) = mv;
            *(float4*)(osum + sidx)     = lv;
            *(float4*)(osum + sidx + 4) = lv;
        }
    }
}

extern "C" void kernel_launch(void* const* d_in, const int* in_sizes, int n_in,
                              void* d_out, int out_size)
{
    const float* q = (const float*)d_in[0];
    const float* k = (const float*)d_in[1];
    const float* v = (const float*)d_in[2];

    float* out  = (float*)d_out;
    float* omax = out + (size_t)32 * 2048 * 128;           // 8388608
    float* osum = omax + (size_t)32 * 2048 * 8;            // +524288

    int smem_bytes = SMEM_FLOATS * sizeof(float);          // 120832 B
    cudaFuncSetAttribute(fa_causal_kernel,
                         cudaFuncAttributeMaxDynamicSharedMemorySize,
                         smem_bytes);

    dim3 grid(S_LEN / BM, 32);   // (32 q-tiles, 32 heads)
    dim3 block(NTHREADS);
    fa_causal_kernel<<<grid, block, smem_bytes>>>(q, k, v, out, omax, osum);
}

// round 3
// speedup vs baseline: 2.6367x; 2.6367x over previous
#include <cuda_runtime.h>
#include <cuda_bf16.h>
#include <cstdint>

// FlashAttentionScore B=2,N=16,S=2048,D=128 fp32 causal.
// Legacy tensor-core path: mma.sync m16n8k16 bf16, hi/lo 3-term split.
// out layout: [out 32*2048*128][max x8: 32*2048*8][sum x8: 32*2048*8]

#define S_LEN 2048
#define DH    128
#define BM    64
#define BN    64
#define NT    128

#define QK_STRIDE 272            // 128 bf16 = 256B + 16B pad (68 words ≡ 4 mod 32)
#define VT_STRIDE 144            // 64 bf16 = 128B + 16B pad  (36 words ≡ 4 mod 32)
#define SM_QHI 0
#define SM_QLO (64*QK_STRIDE)
#define SM_KHI (2*64*QK_STRIDE)
#define SM_KLO (3*64*QK_STRIDE)
#define SM_VHI (4*64*QK_STRIDE)
#define SM_VLO (SM_VHI + 128*VT_STRIDE)
#define SMEM_BYTES (SM_VLO + 128*VT_STRIDE)   // 106496
#define HLO   (64*QK_STRIDE)     // hi -> lo delta (Q/K)
#define VLO_D (128*VT_STRIDE)    // hi -> lo delta (V^T)

__device__ __forceinline__ float ex2f_(float x){
    float r; asm("ex2.approx.ftz.f32 %0, %1;" : "=f"(r) : "f"(x)); return r;
}
__device__ __forceinline__ uint32_t pk(__nv_bfloat16 a, __nv_bfloat16 b){
    return (uint32_t)__bfloat16_as_ushort(a) | ((uint32_t)__bfloat16_as_ushort(b) << 16);
}
__device__ __forceinline__ void bsplit(float x, __nv_bfloat16& h, __nv_bfloat16& lo){
    h  = __float2bfloat16_rn(x);
    lo = __float2bfloat16_rn(x - __bfloat162float(h));
}
__device__ __forceinline__ void mma16816(float c[4],
        uint32_t a0, uint32_t a1, uint32_t a2, uint32_t a3,
        uint32_t b0, uint32_t b1){
    asm volatile(
        "mma.sync.aligned.m16n8k16.row.col.f32.bf16.bf16.f32 "
        "{%0,%1,%2,%3}, {%4,%5,%6,%7}, {%8,%9}, {%0,%1,%2,%3};"
        : "+f"(c[0]), "+f"(c[1]), "+f"(c[2]), "+f"(c[3])
        : "r"(a0), "r"(a1), "r"(a2), "r"(a3), "r"(b0), "r"(b1));
}

__global__ void __launch_bounds__(NT, 2)
fa_mma_kernel(const float* __restrict__ q, const float* __restrict__ k,
              const float* __restrict__ v, float* __restrict__ out,
              float* __restrict__ omax, float* __restrict__ osum)
{
    extern __shared__ char sm[];
    const int t = threadIdx.x;
    const int l = t & 31;
    const int w = t >> 5;
    const int h = blockIdx.y;
    const int qt = 31 - (int)blockIdx.x;   // big tiles first
    const int nkt = qt + 1;

    const float QSCALE = 0.08838834764831845f * 1.4426950408889634f; // scale*log2e

    // ---- Q -> smem bf16 hi/lo (pre-scaled), once ----
    {
        const float4* Q4 = (const float4*)(q + ((size_t)h * S_LEN + (size_t)qt * BM) * DH);
#pragma unroll
        for (int i = 0; i < 16; ++i){
            int idx = t + NT * i;
            int row = idx >> 5, c4 = idx & 31;
            float4 f = Q4[idx];
            f.x *= QSCALE; f.y *= QSCALE; f.z *= QSCALE; f.w *= QSCALE;
            __nv_bfloat16 hx,lx,hy,ly,hz,lz,hw,lw;
            bsplit(f.x,hx,lx); bsplit(f.y,hy,ly); bsplit(f.z,hz,lz); bsplit(f.w,hw,lw);
            char* p = sm + SM_QHI + row * QK_STRIDE + c4 * 8;
            *(uint2*)p         = make_uint2(pk(hx,hy), pk(hz,hw));
            *(uint2*)(p + HLO) = make_uint2(pk(lx,ly), pk(lz,lw));
        }
    }

    float o[16][4];
#pragma unroll
    for (int i = 0; i < 16; ++i){ o[i][0]=o[i][1]=o[i][2]=o[i][3]=0.f; }
    float m0=-1e30f, m1=-1e30f, l0=0.f, l1=0.f;

    const uint32_t qa  = SM_QHI + (16*w + (l>>2)) * QK_STRIDE + (l&3)*4;
    const uint32_t kbb = SM_KHI + (l>>2) * QK_STRIDE + (l&3)*4;
    const uint32_t vbb = SM_VHI + (l>>2) * VT_STRIDE + (l&3)*4;

    const float* Kh = k + (size_t)h * S_LEN * DH;
    const float* Vh = v + (size_t)h * S_LEN * DH;
    const int rot = l >> 3;

    for (int kt = 0; kt < nkt; ++kt){
        __syncthreads();   // previous tile's fragment reads done (also covers Q store)

        // ---- K tile -> smem hi/lo ----
        {
            const float4* K4 = (const float4*)(Kh + (size_t)kt * BN * DH);
#pragma unroll
            for (int i = 0; i < 16; ++i){
                int idx = t + NT * i;
                int row = idx >> 5, c4 = idx & 31;
                float4 f = K4[idx];
                __nv_bfloat16 hx,lx,hy,ly,hz,lz,hw,lw;
                bsplit(f.x,hx,lx); bsplit(f.y,hy,ly); bsplit(f.z,hz,lz); bsplit(f.w,hw,lw);
                char* p = sm + SM_KHI + row * QK_STRIDE + c4 * 8;
                *(uint2*)p         = make_uint2(pk(hx,hy), pk(hz,hw));
                *(uint2*)(p + HLO) = make_uint2(pk(lx,ly), pk(lz,lw));
            }
        }
        // ---- V tile -> smem transposed [n][k] hi/lo ----
        {
            const float* Vt = Vh + (size_t)kt * BN * DH;
#pragma unroll
            for (int i = 0; i < 16; ++i){
                int kq = 4 * ((i + rot) & 15);
                float a0 = Vt[(kq+0)*DH + t];
                float a1 = Vt[(kq+1)*DH + t];
                float a2 = Vt[(kq+2)*DH + t];
                float a3 = Vt[(kq+3)*DH + t];
                __nv_bfloat16 h0,g0,h1,g1,h2,g2,h3,g3;
                bsplit(a0,h0,g0); bsplit(a1,h1,g1); bsplit(a2,h2,g2); bsplit(a3,h3,g3);
                char* p = sm + SM_VHI + t * VT_STRIDE + kq * 2;
                *(uint2*)p           = make_uint2(pk(h0,h1), pk(h2,h3));
                *(uint2*)(p + VLO_D) = make_uint2(pk(g0,g1), pk(g2,g3));
            }
        }
        __syncthreads();

        // ---- S = Q K^T (3-term bf16) ----
        float c[8][4];
#pragma unroll
        for (int i = 0; i < 8; ++i){ c[i][0]=c[i][1]=c[i][2]=c[i][3]=0.f; }
#pragma unroll
        for (int kk = 0; kk < 8; ++kk){
            uint32_t qo = qa + kk*32;
            uint32_t a0h = *(const uint32_t*)(sm + qo);
            uint32_t a1h = *(const uint32_t*)(sm + qo + 8*QK_STRIDE);
            uint32_t a2h = *(const uint32_t*)(sm + qo + 16);
            uint32_t a3h = *(const uint32_t*)(sm + qo + 8*QK_STRIDE + 16);
            uint32_t a0l = *(const uint32_t*)(sm + qo + HLO);
            uint32_t a1l = *(const uint32_t*)(sm + qo + HLO + 8*QK_STRIDE);
            uint32_t a2l = *(const uint32_t*)(sm + qo + HLO + 16);
            uint32_t a3l = *(const uint32_t*)(sm + qo + HLO + 8*QK_STRIDE + 16);
#pragma unroll
            for (int nt = 0; nt < 8; ++nt){
                uint32_t ko = kbb + nt*(8*QK_STRIDE) + kk*32;
                uint32_t b0h = *(const uint32_t*)(sm + ko);
                uint32_t b1h = *(const uint32_t*)(sm + ko + 16);
                uint32_t b0l = *(const uint32_t*)(sm + ko + HLO);
                uint32_t b1l = *(const uint32_t*)(sm + ko + HLO + 16);
                mma16816(c[nt], a0h,a1h,a2h,a3h, b0h,b1h);
                mma16816(c[nt], a0l,a1l,a2l,a3l, b0h,b1h);
                mma16816(c[nt], a0h,a1h,a2h,a3h, b0l,b1l);
            }
        }

        // ---- causal mask (diagonal tile only) ----
        if (kt == qt){
            int gr0 = qt*BM + 16*w + (l>>2);
            int cb  = kt*BN + 2*(l&3);
#pragma unroll
            for (int nt = 0; nt < 8; ++nt){
                int gc = cb + 8*nt;
                if (gc   > gr0)   c[nt][0] = -1e30f;
                if (gc+1 > gr0)   c[nt][1] = -1e30f;
                if (gc   > gr0+8) c[nt][2] = -1e30f;
                if (gc+1 > gr0+8) c[nt][3] = -1e30f;
            }
        }

        // ---- online softmax (log2 domain; rows r=16w+(l>>2), r+8) ----
        float tm0 = -1e30f, tm1 = -1e30f;
#pragma unroll
        for (int nt = 0; nt < 8; ++nt){
            tm0 = fmaxf(tm0, fmaxf(c[nt][0], c[nt][1]));
            tm1 = fmaxf(tm1, fmaxf(c[nt][2], c[nt][3]));
        }
        tm0 = fmaxf(tm0, __shfl_xor_sync(0xffffffffu, tm0, 1));
        tm0 = fmaxf(tm0, __shfl_xor_sync(0xffffffffu, tm0, 2));
        tm1 = fmaxf(tm1, __shfl_xor_sync(0xffffffffu, tm1, 1));
        tm1 = fmaxf(tm1, __shfl_xor_sync(0xffffffffu, tm1, 2));
        float mn0 = fmaxf(m0, tm0), mn1 = fmaxf(m1, tm1);
        float al0 = ex2f_(m0 - mn0), al1 = ex2f_(m1 - mn1);
        m0 = mn0; m1 = mn1;

        uint32_t phi[16], plo[16];
        float rs0 = 0.f, rs1 = 0.f;
#pragma unroll
        for (int nt = 0; nt < 8; ++nt){
            float p0 = ex2f_(c[nt][0]-mn0), p1 = ex2f_(c[nt][1]-mn0);
            float p2 = ex2f_(c[nt][2]-mn1), p3 = ex2f_(c[nt][3]-mn1);
            rs0 += p0 + p1; rs1 += p2 + p3;
            __nv_bfloat16 h0,g0,h1,g1,h2,g2,h3,g3;
            bsplit(p0,h0,g0); bsplit(p1,h1,g1); bsplit(p2,h2,g2); bsplit(p3,h3,g3);
            int base = (nt >> 1)*4 + (nt & 1)*2;
            phi[base]   = pk(h0,h1);  phi[base+1] = pk(h2,h3);
            plo[base]   = pk(g0,g1);  plo[base+1] = pk(g2,g3);
        }
        rs0 += __shfl_xor_sync(0xffffffffu, rs0, 1);
        rs0 += __shfl_xor_sync(0xffffffffu, rs0, 2);
        rs1 += __shfl_xor_sync(0xffffffffu, rs1, 1);
        rs1 += __shfl_xor_sync(0xffffffffu, rs1, 2);
        l0 = l0*al0 + rs0; l1 = l1*al1 + rs1;

#pragma unroll
        for (int i = 0; i < 16; ++i){
            o[i][0] *= al0; o[i][1] *= al0; o[i][2] *= al1; o[i][3] *= al1;
        }

        // ---- O += P V (3-term bf16) ----
#pragma unroll
        for (int kkp = 0; kkp < 4; ++kkp){
            uint32_t pa0 = phi[4*kkp], pa1 = phi[4*kkp+1], pa2 = phi[4*kkp+2], pa3 = phi[4*kkp+3];
            uint32_t pl0 = plo[4*kkp], pl1 = plo[4*kkp+1], pl2 = plo[4*kkp+2], pl3 = plo[4*kkp+3];
#pragma unroll
            for (int nt2 = 0; nt2 < 16; ++nt2){
                uint32_t vo = vbb + nt2*(8*VT_STRIDE) + kkp*32;
                uint32_t b0h = *(const uint32_t*)(sm + vo);
                uint32_t b1h = *(const uint32_t*)(sm + vo + 16);
                uint32_t b0l = *(const uint32_t*)(sm + vo + VLO_D);
                uint32_t b1l = *(const uint32_t*)(sm + vo + VLO_D + 16);
                mma16816(o[nt2], pa0,pa1,pa2,pa3, b0h,b1h);
                mma16816(o[nt2], pl0,pl1,pl2,pl3, b0h,b1h);
                mma16816(o[nt2], pa0,pa1,pa2,pa3, b0l,b1l);
            }
        }
    }

    // ---- epilogue ----
    float inv0 = 1.f / l0, inv1 = 1.f / l1;
    int r0 = qt*BM + 16*w + (l>>2);
    float* po = out + ((size_t)h * S_LEN + r0) * DH + 2*(l&3);
#pragma unroll
    for (int nt2 = 0; nt2 < 16; ++nt2){
        *(float2*)(po + 8*nt2)          = make_float2(o[nt2][0]*inv0, o[nt2][1]*inv0);
        *(float2*)(po + 8*DH + 8*nt2)   = make_float2(o[nt2][2]*inv1, o[nt2][3]*inv1);
    }
    if ((l & 3) == 0){
        const float LN2 = 0.6931471805599453f;
        size_t s0 = ((size_t)h * S_LEN + r0) * 8;
        size_t s1 = s0 + 64;   // row + 8
        float mn0 = m0 * LN2, mn1 = m1 * LN2;
        float4 mv0 = make_float4(mn0, mn0, mn0, mn0);
        float4 mv1 = make_float4(mn1, mn1, mn1, mn1);
        float4 lv0 = make_float4(l0, l0, l0, l0);
        float4 lv1 = make_float4(l1, l1, l1, l1);
        *(float4*)(omax + s0) = mv0; *(float4*)(omax + s0 + 4) = mv0;
        *(float4*)(omax + s1) = mv1; *(float4*)(omax + s1 + 4) = mv1;
        *(float4*)(osum + s0) = lv0; *(float4*)(osum + s0 + 4) = lv0;
        *(float4*)(osum + s1) = lv1; *(float4*)(osum + s1 + 4) = lv1;
    }
}

extern "C" void kernel_launch(void* const* d_in, const int* in_sizes, int n_in,
                              void* d_out, int out_size)
{
    const float* q = (const float*)d_in[0];
    const float* k = (const float*)d_in[1];
    const float* v = (const float*)d_in[2];

    float* out  = (float*)d_out;
    float* omax = out + (size_t)32 * 2048 * 128;
    float* osum = omax + (size_t)32 * 2048 * 8;

    cudaFuncSetAttribute(fa_mma_kernel,
                         cudaFuncAttributeMaxDynamicSharedMemorySize, SMEM_BYTES);
    dim3 grid(32, 32);   // (q-tiles, heads)
    fa_mma_kernel<<<grid, NT, SMEM_BYTES>>>(q, k, v, out, omax, osum);
}